// round 3
// baseline (speedup 1.0000x reference)
#include <cuda_runtime.h>

// SparseTransE on GB300.
// Inputs (metadata order):
//   d_in[0] all_emb  : float32 [501000, 256]
//   d_in[1] pos_h    : int32   [65536]
//   d_in[2] pos_r    : int32   [65536]
//   d_in[3] pos_t    : int32   [65536]
//   d_in[4] neg_h    : int32   [65536]
//   d_in[5] neg_r    : int32   [65536]
//   d_in[6] neg_t    : int32   [65536]
//   d_in[7] n_ent    : scalar (500000, fixed by the problem)
// Output: float32 [131072] = concat(pos_scores, neg_scores)
//
// score(h,r,t) = -|| e[h]/max(||e[h]||,eps) + e[r+n_ent] - e[t]/max(||e[t]||,eps) ||^2
//
// Key optimization vs reference: never materialize the normalized 500k-row
// table; normalize only the gathered rows on the fly (saves ~1 GB of
// read+write traffic). One warp per triple, float4 gathers, two warp
// butterfly reductions.

#define N_BATCH 65536
#define EMB     256
#define N_ENT   500000
#define EPS2    1e-24f   // (1e-12)^2 — guard matches max(norm, 1e-12)

__global__ __launch_bounds__(256, 8)
void sparse_transe_kernel(
    const float* __restrict__ emb,
    const int*   __restrict__ pos_h,
    const int*   __restrict__ pos_r,
    const int*   __restrict__ pos_t,
    const int*   __restrict__ neg_h,
    const int*   __restrict__ neg_r,
    const int*   __restrict__ neg_t,
    float*       __restrict__ out)
{
    const int gwarp = (blockIdx.x * blockDim.x + threadIdx.x) >> 5;
    const int lane  = threadIdx.x & 31;
    if (gwarp >= 2 * N_BATCH) return;

    const int* __restrict__ H;
    const int* __restrict__ R;
    const int* __restrict__ T;
    int i;
    if (gwarp < N_BATCH) { H = pos_h; R = pos_r; T = pos_t; i = gwarp; }
    else                 { H = neg_h; R = neg_r; T = neg_t; i = gwarp - N_BATCH; }

    // Scalar index loads — same address across warp, broadcast via L1.
    const long hrow = (long)__ldg(&H[i]) * EMB;
    const long rrow = ((long)__ldg(&R[i]) + N_ENT) * EMB;
    const long trow = (long)__ldg(&T[i]) * EMB;

    // Each row = 64 float4. Lane covers float4 indices {lane, lane+32}.
    const float4* __restrict__ hp = (const float4*)(emb + hrow);
    const float4* __restrict__ rp = (const float4*)(emb + rrow);
    const float4* __restrict__ tp = (const float4*)(emb + trow);

    // Issue all 6 loads back-to-back for max MLP.
    float4 h0 = hp[lane];
    float4 h1 = hp[lane + 32];
    float4 t0 = tp[lane];
    float4 t1 = tp[lane + 32];
    float4 r0 = rp[lane];
    float4 r1 = rp[lane + 32];

    // Partial squared norms of h and t.
    float sh = h0.x*h0.x + h0.y*h0.y + h0.z*h0.z + h0.w*h0.w
             + h1.x*h1.x + h1.y*h1.y + h1.z*h1.z + h1.w*h1.w;
    float st = t0.x*t0.x + t0.y*t0.y + t0.z*t0.z + t0.w*t0.w
             + t1.x*t1.x + t1.y*t1.y + t1.z*t1.z + t1.w*t1.w;

    // Fused butterfly reduction of (sh, st).
    #pragma unroll
    for (int off = 16; off > 0; off >>= 1) {
        sh += __shfl_xor_sync(0xffffffffu, sh, off);
        st += __shfl_xor_sync(0xffffffffu, st, off);
    }

    const float inv_h = rsqrtf(fmaxf(sh, EPS2));
    const float inv_t = rsqrtf(fmaxf(st, EPS2));

    // v = h/|h| + r - t/|t| ; accumulate v^2
    float acc = 0.f;
    {
        float d;
        d = fmaf(h0.x, inv_h, r0.x) - t0.x * inv_t; acc = fmaf(d, d, acc);
        d = fmaf(h0.y, inv_h, r0.y) - t0.y * inv_t; acc = fmaf(d, d, acc);
        d = fmaf(h0.z, inv_h, r0.z) - t0.z * inv_t; acc = fmaf(d, d, acc);
        d = fmaf(h0.w, inv_h, r0.w) - t0.w * inv_t; acc = fmaf(d, d, acc);
        d = fmaf(h1.x, inv_h, r1.x) - t1.x * inv_t; acc = fmaf(d, d, acc);
        d = fmaf(h1.y, inv_h, r1.y) - t1.y * inv_t; acc = fmaf(d, d, acc);
        d = fmaf(h1.z, inv_h, r1.z) - t1.z * inv_t; acc = fmaf(d, d, acc);
        d = fmaf(h1.w, inv_h, r1.w) - t1.w * inv_t; acc = fmaf(d, d, acc);
    }

    #pragma unroll
    for (int off = 16; off > 0; off >>= 1)
        acc += __shfl_xor_sync(0xffffffffu, acc, off);

    if (lane == 0)
        out[gwarp] = -acc;
}

extern "C" void kernel_launch(void* const* d_in, const int* in_sizes, int n_in,
                              void* d_out, int out_size)
{
    const float* emb   = (const float*)d_in[0];
    const int*   pos_h = (const int*)d_in[1];
    const int*   pos_r = (const int*)d_in[2];
    const int*   pos_t = (const int*)d_in[3];
    const int*   neg_h = (const int*)d_in[4];
    const int*   neg_r = (const int*)d_in[5];
    const int*   neg_t = (const int*)d_in[6];
    float* out = (float*)d_out;

    // 2*65536 warps, 8 warps (256 threads) per block.
    const int total_warps = 2 * N_BATCH;
    const int warps_per_block = 8;
    const int blocks = total_warps / warps_per_block;  // 16384
    sparse_transe_kernel<<<blocks, warps_per_block * 32>>>(
        emb, pos_h, pos_r, pos_t, neg_h, neg_r, neg_t, out);
}